// round 11
// baseline (speedup 1.0000x reference)
#include <cuda_runtime.h>
#include <cstdint>

#define N_NODES 10000
#define N_EDGES 100000
#define F 64
#define NTYPES 10
#define WT_ELEMS (NTYPES * F * F)        // 40960 floats = 160KB
#define GRP 8                             // edges per warp group (same type)
#define SEG_CAP 12288                     // per-type segment capacity
#define EDGE_THREADS 512
#define EDGE_WARPS (EDGE_THREADS / 32)    // 16
#define SH_H_FLOATS (EDGE_WARPS * GRP * F)        // 8192 floats = 32KB
#define SMEM_EDGE_BYTES ((WT_ELEMS + SH_H_FLOATS) * 4)   // 192KB

// ---- device scratch (no allocs allowed) ----
__device__ float g_deg_out[N_NODES];
__device__ float g_deg_in[N_NODES];
__device__ float g_wt[WT_ELEMS];               // pre-interleaved weights
__device__ int   g_esrc[NTYPES * SEG_CAP];     // type-segmented src
__device__ int   g_edst[NTYPES * SEG_CAP];     // type-segmented dst
__device__ int   g_cursor[NTYPES];             // per-type counts

// ------------------------------------------------------------------
// Kernel 1: acc := bias (folds the final bias add away), zero degrees
// and cursors, pre-interleave W.
// Interleaved layout: per type r, float4 wv[j][L] =
//   { w[2j][2L], w[2j+1][2L], w[2j][2L+1], w[2j+1][2L+1] }
__global__ void rconv_init(float4* __restrict__ acc4, const float* __restrict__ emb,
                           const float4* __restrict__ bias4) {
    int stride = gridDim.x * blockDim.x;
    int tid = blockIdx.x * blockDim.x + threadIdx.x;
    for (int i = tid; i < N_NODES * F / 4; i += stride)
        acc4[i] = bias4[i & 15];
    for (int j = tid; j < N_NODES; j += stride) { g_deg_out[j] = 0.f; g_deg_in[j] = 0.f; }
    for (int idx = tid; idx < WT_ELEMS; idx += stride) {
        int r   = idx >> 12;
        int rem = idx & 4095;
        int j   = rem >> 7;       // input-pair index 0..31
        int pos = rem & 127;
        int L   = pos >> 2;       // lane
        int c   = pos & 3;
        int o   = 2 * L + (c >> 1);
        int i   = 2 * j + (c & 1);
        g_wt[idx] = emb[(r << 12) + (o << 6) + i];
    }
    if (tid < NTYPES) g_cursor[tid] = 0;
}

// ------------------------------------------------------------------
// Kernel 2: fused degrees + single-pass type-segmented scatter.
__global__ void rconv_count_scatter(const int* __restrict__ src,
                                    const int* __restrict__ dst,
                                    const int* __restrict__ order) {
    const int lane = threadIdx.x & 31;
    int e = blockIdx.x * blockDim.x + threadIdx.x;
    bool v = e < N_EDGES;
    unsigned act = __ballot_sync(0xffffffffu, v);
    if (v) {
        int s = src[e], d = dst[e], t = order[e];
        atomicAdd(&g_deg_out[s], 1.0f);
        atomicAdd(&g_deg_in[d], 1.0f);
        unsigned m = __match_any_sync(act, t);
        int leader = __ffs(m) - 1;
        int rank = __popc(m & ((1u << lane) - 1));
        int base = 0;
        if (lane == leader) base = atomicAdd(&g_cursor[t], __popc(m));
        base = __shfl_sync(m, base, leader);
        int pos = t * SEG_CAP + base + rank;
        g_esrc[pos] = s;
        g_edst[pos] = d;
    }
}

// ------------------------------------------------------------------
// Kernel 3: main edge kernel, software-pipelined.
// While computing group gi, the next group's indices + out-deg-scaled
// feature vectors are prefetched into registers, hiding the two-deep
// LDG chain (esrc -> feat) behind FFMA2/LDS work.
// Epilogue scales messages by in_deg^{-1/2}(dst) (uniform per edge) so no
// separate post-norm kernel is needed.
__global__ __launch_bounds__(EDGE_THREADS, 1) void rconv_edges(
    const float2* __restrict__ feat2, float* __restrict__ acc)
{
    extern __shared__ float smem[];
    float* wt  = smem;                 // [NTYPES][32][128] floats (interleaved)
    float* shh = smem + WT_ELEMS;      // [EDGE_WARPS][GRP][64] floats

    {   // coalesced float4 copy of pre-interleaved weights
        const float4* __restrict__ w4 = (const float4*)g_wt;
        float4* wt4 = (float4*)wt;
        for (int i = threadIdx.x; i < WT_ELEMS / 4; i += blockDim.x)
            wt4[i] = w4[i];
    }
    __shared__ int s_lim[NTYPES];        // segment end index (base + count)
    __shared__ int s_goff[NTYPES + 1];   // group prefix
    if (threadIdx.x == 0) {
        int g = 0;
        for (int t = 0; t < NTYPES; t++) {
            int h = g_cursor[t];
            s_lim[t] = t * SEG_CAP + h;
            s_goff[t] = g;
            g += (h + GRP - 1) / GRP;
        }
        s_goff[NTYPES] = g;
    }
    __syncthreads();

    const int lane   = threadIdx.x & 31;
    const int wl     = threadIdx.x >> 5;
    const int warp   = (blockIdx.x * blockDim.x + threadIdx.x) >> 5;
    const int nwarps = (gridDim.x * blockDim.x) >> 5;
    const int n_groups = s_goff[NTYPES];
    float2* myh = (float2*)(shh + wl * (GRP * F));   // [GRP][32] float2

    // ---- group descriptor helper (ALU only) ----
    auto locate = [&](int gi, int& t, int& base, int& lim) {
        t = 0;
        while (gi >= s_goff[t + 1]) t++;
        base = t * SEG_CAP + (gi - s_goff[t]) * GRP;
        lim  = s_lim[t];
    };

    int gi = warp;
    if (gi >= n_groups) return;

    int t, base, lim;
    locate(gi, t, base, lim);

    // prologue: load first group's indices + scaled features into registers
    int    dd[GRP];
    float2 hv[GRP];
    #pragma unroll
    for (int k = 0; k < GRP; k++) {
        int idx = min(base + k, lim - 1);
        int s = __ldg(&g_esrc[idx]);
        dd[k] = __ldg(&g_edst[idx]);
        float sc = rsqrtf(fmaxf(__ldg(&g_deg_out[s]), 1.0f));
        float2 v = feat2[s * 32 + lane];
        hv[k] = make_float2(v.x * sc, v.y * sc);
    }

    while (true) {
        // stage current group's h to per-warp smem
        __syncwarp();
        #pragma unroll
        for (int k = 0; k < GRP; k++)
            myh[k * 32 + lane] = hv[k];
        __syncwarp();

        // kick next group's loads (independent of current compute)
        const int gin = gi + nwarps;
        int tn = 0, basen = 0, limn = 0;
        int    dd2[GRP];
        float2 hv2[GRP];
        if (gin < n_groups) {
            locate(gin, tn, basen, limn);
            #pragma unroll
            for (int k = 0; k < GRP; k++) {
                int idx = min(basen + k, limn - 1);
                int s = __ldg(&g_esrc[idx]);
                dd2[k] = __ldg(&g_edst[idx]);
                float sc = rsqrtf(fmaxf(__ldg(&g_deg_out[s]), 1.0f));
                float2 v = feat2[s * 32 + lane];
                hv2[k] = make_float2(v.x * sc, v.y * sc);
            }
        }

        // compute current group
        const ulonglong2* __restrict__ wv = (const ulonglong2*)(wt + (t << 12));
        const ulonglong2* __restrict__ hp = (const ulonglong2*)myh;  // [GRP][16]
        uint64_t a0[GRP], a1[GRP];
        #pragma unroll
        for (int k = 0; k < GRP; k++) { a0[k] = 0ull; a1[k] = 0ull; }

        #pragma unroll
        for (int j2 = 0; j2 < 16; j2++) {
            const ulonglong2 w0 = wv[(2 * j2) * 32 + lane];
            const ulonglong2 w1 = wv[(2 * j2 + 1) * 32 + lane];
            #pragma unroll
            for (int k = 0; k < GRP; k++) {
                const ulonglong2 h = hp[k * 16 + j2];
                asm("fma.rn.f32x2 %0, %1, %2, %0;" : "+l"(a0[k]) : "l"(w0.x), "l"(h.x));
                asm("fma.rn.f32x2 %0, %1, %2, %0;" : "+l"(a1[k]) : "l"(w0.y), "l"(h.x));
                asm("fma.rn.f32x2 %0, %1, %2, %0;" : "+l"(a0[k]) : "l"(w1.x), "l"(h.y));
                asm("fma.rn.f32x2 %0, %1, %2, %0;" : "+l"(a1[k]) : "l"(w1.y), "l"(h.y));
            }
        }

        // epilogue: scale by in_deg^{-1/2}(dst), pair lanes, red.v4
        #pragma unroll
        for (int k = 0; k < GRP; k++) {
            float sin_ = rsqrtf(fmaxf(__ldg(&g_deg_in[dd[k]]), 1.0f));
            float p, q, r2, s2;
            asm("mov.b64 {%0, %1}, %2;" : "=f"(p),  "=f"(q)  : "l"(a0[k]));
            asm("mov.b64 {%0, %1}, %2;" : "=f"(r2), "=f"(s2) : "l"(a1[k]));
            float ax = (p + q) * sin_;     // output 2L
            float ay = (r2 + s2) * sin_;   // output 2L+1
            float bx = __shfl_down_sync(0xffffffffu, ax, 1);
            float by = __shfl_down_sync(0xffffffffu, ay, 1);
            if ((base + k) < lim && !(lane & 1)) {
                float* ptr = &acc[dd[k] * F + 2 * lane];
                asm volatile("red.global.add.v4.f32 [%0], {%1, %2, %3, %4};"
                             :: "l"(ptr), "f"(ax), "f"(ay), "f"(bx), "f"(by)
                             : "memory");
            }
        }

        if (gin >= n_groups) break;
        gi = gin; t = tn; base = basen; lim = limn;
        #pragma unroll
        for (int k = 0; k < GRP; k++) { dd[k] = dd2[k]; hv[k] = hv2[k]; }
    }
}

extern "C" void kernel_launch(void* const* d_in, const int* in_sizes, int n_in,
                              void* d_out, int out_size) {
    const float* feat = (const float*)d_in[0];
    const int*   src  = (const int*)  d_in[1];
    const int*   dst  = (const int*)  d_in[2];
    const int*   ordr = (const int*)  d_in[3];
    const float* emb  = (const float*)d_in[4];
    const float* bias = (const float*)d_in[5];
    float* out = (float*)d_out;

    static bool attr_set = false;
    if (!attr_set) {
        cudaFuncSetAttribute(rconv_edges,
                             cudaFuncAttributeMaxDynamicSharedMemorySize,
                             SMEM_EDGE_BYTES);
        attr_set = true;
    }

    rconv_init<<<256, 256>>>((float4*)out, emb, (const float4*)bias);
    rconv_count_scatter<<<(N_EDGES + 255) / 256, 256>>>(src, dst, ordr);
    rconv_edges<<<148, EDGE_THREADS, SMEM_EDGE_BYTES>>>((const float2*)feat, out);
}

// round 12
// speedup vs baseline: 1.0477x; 1.0477x over previous
#include <cuda_runtime.h>
#include <cstdint>

#define N_NODES 10000
#define N_EDGES 100000
#define F 64
#define NTYPES 10
#define WT_ELEMS (NTYPES * F * F)        // 40960 floats = 160KB
#define GRP 8                             // edges per warp group (same type)
#define SEG_CAP 12288                     // per-type segment capacity
#define EDGE_THREADS 768
#define EDGE_WARPS (EDGE_THREADS / 32)    // 24
#define SH_H_FLOATS (EDGE_WARPS * GRP * F)        // 12288 floats = 48KB
#define SMEM_EDGE_BYTES ((WT_ELEMS + SH_H_FLOATS) * 4)   // 208KB

// ---- device scratch (no allocs allowed) ----
__device__ float g_deg_out[N_NODES];
__device__ float g_deg_in[N_NODES];
__device__ float g_wt[WT_ELEMS];               // pre-interleaved weights
__device__ int   g_esrc[NTYPES * SEG_CAP];     // type-segmented src
__device__ int   g_edst[NTYPES * SEG_CAP];     // type-segmented dst
__device__ int   g_cursor[NTYPES];             // per-type counts

// ------------------------------------------------------------------
// Kernel 1: acc := bias (folds the final bias add), zero degrees/cursors,
// pre-interleave W into g_wt.
// Interleaved layout: per type r, float4 wv[j][L] =
//   { w[2j][2L], w[2j+1][2L], w[2j][2L+1], w[2j+1][2L+1] }
__global__ void rconv_init(float4* __restrict__ acc4, const float* __restrict__ emb,
                           const float4* __restrict__ bias4) {
    int stride = gridDim.x * blockDim.x;
    int tid = blockIdx.x * blockDim.x + threadIdx.x;
    for (int i = tid; i < N_NODES * F / 4; i += stride)
        acc4[i] = bias4[i & 15];
    for (int j = tid; j < N_NODES; j += stride) { g_deg_out[j] = 0.f; g_deg_in[j] = 0.f; }
    for (int idx = tid; idx < WT_ELEMS; idx += stride) {
        int r   = idx >> 12;
        int rem = idx & 4095;
        int j   = rem >> 7;       // input-pair index 0..31
        int pos = rem & 127;
        int L   = pos >> 2;       // lane
        int c   = pos & 3;
        int o   = 2 * L + (c >> 1);
        int i   = 2 * j + (c & 1);
        g_wt[idx] = emb[(r << 12) + (o << 6) + i];
    }
    if (tid < NTYPES) g_cursor[tid] = 0;
}

// ------------------------------------------------------------------
// Kernel 2: fused degrees + single-pass type-segmented scatter.
// Fixed-capacity segments; warp-aggregated cursor atomics.
__global__ void rconv_count_scatter(const int* __restrict__ src,
                                    const int* __restrict__ dst,
                                    const int* __restrict__ order) {
    const int lane = threadIdx.x & 31;
    int e = blockIdx.x * blockDim.x + threadIdx.x;
    bool v = e < N_EDGES;
    unsigned act = __ballot_sync(0xffffffffu, v);
    if (v) {
        int s = src[e], d = dst[e], t = order[e];
        atomicAdd(&g_deg_out[s], 1.0f);
        atomicAdd(&g_deg_in[d], 1.0f);
        unsigned m = __match_any_sync(act, t);
        int leader = __ffs(m) - 1;
        int rank = __popc(m & ((1u << lane) - 1));
        int base = 0;
        if (lane == leader) base = atomicAdd(&g_cursor[t], __popc(m));
        base = __shfl_sync(m, base, leader);
        int pos = t * SEG_CAP + base + rank;
        g_esrc[pos] = s;
        g_edst[pos] = d;
    }
}

// ------------------------------------------------------------------
// Kernel 3: main edge kernel (R10 structure: no software pipeline, 24 warps).
// Stage pre-interleaved W (coalesced float4), gather h with inline
// out_deg^{-1/2} scaling into per-warp smem, packed fma.rn.f32x2 inner
// product with both operands straight from LDS.128.
// Epilogue scales by in_deg^{-1/2}(dst) and emits red.global.add.v4.f32
// from even lanes (bias already folded into the accumulator by init).
__global__ __launch_bounds__(EDGE_THREADS, 1) void rconv_edges(
    const float2* __restrict__ feat2, float* __restrict__ acc)
{
    extern __shared__ float smem[];
    float* wt  = smem;                 // [NTYPES][32][128] floats (interleaved)
    float* shh = smem + WT_ELEMS;      // [EDGE_WARPS][GRP][64] floats

    {   // coalesced float4 copy of pre-interleaved weights
        const float4* __restrict__ w4 = (const float4*)g_wt;
        float4* wt4 = (float4*)wt;
        for (int i = threadIdx.x; i < WT_ELEMS / 4; i += blockDim.x)
            wt4[i] = w4[i];
    }
    __shared__ int s_lim[NTYPES];        // segment end index (base + count)
    __shared__ int s_goff[NTYPES + 1];   // group prefix
    if (threadIdx.x == 0) {
        int g = 0;
        for (int t = 0; t < NTYPES; t++) {
            int h = g_cursor[t];
            s_lim[t] = t * SEG_CAP + h;
            s_goff[t] = g;
            g += (h + GRP - 1) / GRP;
        }
        s_goff[NTYPES] = g;
    }
    __syncthreads();

    const int lane   = threadIdx.x & 31;
    const int wl     = threadIdx.x >> 5;
    const int warp   = (blockIdx.x * blockDim.x + threadIdx.x) >> 5;
    const int nwarps = (gridDim.x * blockDim.x) >> 5;
    const int n_groups = s_goff[NTYPES];
    float2* myh = (float2*)(shh + wl * (GRP * F));   // [GRP][32] float2

    for (int gi = warp; gi < n_groups; gi += nwarps) {
        int t = 0;
        while (gi >= s_goff[t + 1]) t++;
        const int base = t * SEG_CAP + (gi - s_goff[t]) * GRP;
        const int lim  = s_lim[t];

        __syncwarp();   // previous iteration's readers done before overwrite
        int dd[GRP];
        #pragma unroll
        for (int k = 0; k < GRP; k++) {
            int idx = min(base + k, lim - 1);
            int s = __ldg(&g_esrc[idx]);
            dd[k] = __ldg(&g_edst[idx]);
            float sc = rsqrtf(fmaxf(__ldg(&g_deg_out[s]), 1.0f));  // broadcast
            float2 v = feat2[s * 32 + lane];
            myh[k * 32 + lane] = make_float2(v.x * sc, v.y * sc);
        }
        __syncwarp();

        const ulonglong2* __restrict__ wv = (const ulonglong2*)(wt + (t << 12));
        const ulonglong2* __restrict__ hp = (const ulonglong2*)myh;  // [GRP][16]
        uint64_t a0[GRP], a1[GRP];
        #pragma unroll
        for (int k = 0; k < GRP; k++) { a0[k] = 0ull; a1[k] = 0ull; }

        #pragma unroll
        for (int j2 = 0; j2 < 16; j2++) {
            const ulonglong2 w0 = wv[(2 * j2) * 32 + lane];       // j = 2*j2
            const ulonglong2 w1 = wv[(2 * j2 + 1) * 32 + lane];   // j = 2*j2+1
            #pragma unroll
            for (int k = 0; k < GRP; k++) {
                const ulonglong2 h = hp[k * 16 + j2];   // h[4j2..4j2+3] broadcast
                asm("fma.rn.f32x2 %0, %1, %2, %0;" : "+l"(a0[k]) : "l"(w0.x), "l"(h.x));
                asm("fma.rn.f32x2 %0, %1, %2, %0;" : "+l"(a1[k]) : "l"(w0.y), "l"(h.x));
                asm("fma.rn.f32x2 %0, %1, %2, %0;" : "+l"(a0[k]) : "l"(w1.x), "l"(h.y));
                asm("fma.rn.f32x2 %0, %1, %2, %0;" : "+l"(a1[k]) : "l"(w1.y), "l"(h.y));
            }
        }

        #pragma unroll
        for (int k = 0; k < GRP; k++) {
            float sin_ = rsqrtf(fmaxf(__ldg(&g_deg_in[dd[k]]), 1.0f));
            float p, q, r2, s2;
            asm("mov.b64 {%0, %1}, %2;" : "=f"(p),  "=f"(q)  : "l"(a0[k]));
            asm("mov.b64 {%0, %1}, %2;" : "=f"(r2), "=f"(s2) : "l"(a1[k]));
            float ax = (p + q) * sin_;     // output 2L
            float ay = (r2 + s2) * sin_;   // output 2L+1
            float bx = __shfl_down_sync(0xffffffffu, ax, 1);
            float by = __shfl_down_sync(0xffffffffu, ay, 1);
            if ((base + k) < lim && !(lane & 1)) {
                float* ptr = &acc[dd[k] * F + 2 * lane];
                asm volatile("red.global.add.v4.f32 [%0], {%1, %2, %3, %4};"
                             :: "l"(ptr), "f"(ax), "f"(ay), "f"(bx), "f"(by)
                             : "memory");
            }
        }
    }
}

extern "C" void kernel_launch(void* const* d_in, const int* in_sizes, int n_in,
                              void* d_out, int out_size) {
    const float* feat = (const float*)d_in[0];
    const int*   src  = (const int*)  d_in[1];
    const int*   dst  = (const int*)  d_in[2];
    const int*   ordr = (const int*)  d_in[3];
    const float* emb  = (const float*)d_in[4];
    const float* bias = (const float*)d_in[5];
    float* out = (float*)d_out;

    static bool attr_set = false;
    if (!attr_set) {
        cudaFuncSetAttribute(rconv_edges,
                             cudaFuncAttributeMaxDynamicSharedMemorySize,
                             SMEM_EDGE_BYTES);
        attr_set = true;
    }

    rconv_init<<<1184, 256>>>((float4*)out, emb, (const float4*)bias);
    rconv_count_scatter<<<(N_EDGES + 511) / 512, 512>>>(src, dst, ordr);
    rconv_edges<<<148, EDGE_THREADS, SMEM_EDGE_BYTES>>>((const float2*)feat, out);
}